// round 9
// baseline (speedup 1.0000x reference)
#include <cuda_runtime.h>
#include <cuda_fp16.h>
#include <cstdint>

#define NNODES 100000
#define EDGES_MAX 1600000
#define DIM 128
#define SCAN_BLK 512
#define NB_SCAN ((NNODES + SCAN_BLK - 1) / SCAN_BLK)

// ---------------------------------------------------------------------------
// Device-global scratch (no allocations allowed anywhere)
// ---------------------------------------------------------------------------
__device__ __half g_aggh[NNODES * DIM];   // fp16 agg output (GEMM A)
__device__ float  g_agg[NNODES * DIM];    // fallback-path fp32 agg
__device__ int    g_is64;
__device__ __half g_wt1h[DIM * DIM];      // W1^T fp16 [n][k]
__device__ __half g_wt2h[DIM * DIM];      // W2^T fp16 [n][k]
// CSR build
__device__ int g_cnt[NNODES];
__device__ int g_rowptr[NNODES + 1];
__device__ int g_cur[NNODES];
__device__ int g_blksum[NB_SCAN + 8];
__device__ int g_esrc[EDGES_MAX];

// ---------------------------------------------------------------------------
// helpers
// ---------------------------------------------------------------------------
__device__ __forceinline__ uint32_t smem_u32(const void* p) {
    uint32_t a;
    asm("{ .reg .u64 t; cvta.to.shared.u64 t, %1; cvt.u32.u64 %0, t; }"
        : "=r"(a) : "l"(p));
    return a;
}
__device__ __forceinline__ void ldsm4(uint32_t* r, uint32_t addr) {
    asm volatile("ldmatrix.sync.aligned.m8n8.x4.shared.b16 {%0,%1,%2,%3}, [%4];"
                 : "=r"(r[0]), "=r"(r[1]), "=r"(r[2]), "=r"(r[3]) : "r"(addr));
}
__device__ __forceinline__ void mma_f16(float* d, const uint32_t* a,
                                        uint32_t b0, uint32_t b1) {
    asm volatile(
        "mma.sync.aligned.m16n8k16.row.col.f32.f16.f16.f32 "
        "{%0,%1,%2,%3}, {%4,%5,%6,%7}, {%8,%9}, {%0,%1,%2,%3};"
        : "+f"(d[0]), "+f"(d[1]), "+f"(d[2]), "+f"(d[3])
        : "r"(a[0]), "r"(a[1]), "r"(a[2]), "r"(a[3]), "r"(b0), "r"(b1));
}
__device__ __forceinline__ int load_idx(const void* ei, long long pos) {
    return g_is64 ? (int)((const long long*)ei)[pos] : ((const int*)ei)[pos];
}
__device__ __forceinline__ uint32_t pack_h2(float a, float b) {
    __half2 h = __floats2half2_rn(a, b);
    return *reinterpret_cast<uint32_t*>(&h);
}

// ---------------------------------------------------------------------------
// edge_index dtype detection (int64 ids < 2^31 -> odd words all zero)
// ---------------------------------------------------------------------------
__global__ void detect_kernel(const unsigned int* __restrict__ w) {
    if (threadIdx.x == 0 && blockIdx.x == 0) {
        int allzero = 1;
        for (int i = 1; i < 256; i += 2)
            if (w[i] != 0u) { allzero = 0; break; }
        g_is64 = allzero;
    }
}

// ---------------------------------------------------------------------------
// CSR build: histogram -> scan (2 kernels) -> reorder
// g_cnt zeroed by cudaMemsetAsync. rowptr/cur hold block-LOCAL exclusive
// prefixes; consumers add g_blksum[i >> 9].
// ---------------------------------------------------------------------------
__global__ void hist_kernel(const void* __restrict__ ei, int E) {
    int i0 = (blockIdx.x * blockDim.x + threadIdx.x) * 4;
    if (i0 + 4 <= E) {
        int d0 = load_idx(ei, (long long)E + i0);
        int d1 = load_idx(ei, (long long)E + i0 + 1);
        int d2 = load_idx(ei, (long long)E + i0 + 2);
        int d3 = load_idx(ei, (long long)E + i0 + 3);
        atomicAdd(&g_cnt[d0], 1);
        atomicAdd(&g_cnt[d1], 1);
        atomicAdd(&g_cnt[d2], 1);
        atomicAdd(&g_cnt[d3], 1);
    } else {
        for (int i = i0; i < E; i++)
            atomicAdd(&g_cnt[load_idx(ei, (long long)E + i)], 1);
    }
}

__device__ __forceinline__ int warp_incl_scan(int x, int lane) {
#pragma unroll
    for (int off = 1; off < 32; off <<= 1) {
        int y = __shfl_up_sync(0xFFFFFFFFu, x, off);
        if (lane >= off) x += y;
    }
    return x;
}

__global__ void scan1_kernel(int N) {  // 512 threads, 1 elem each
    __shared__ int wsum[16];
    int t = threadIdx.x, b = blockIdx.x;
    int lane = t & 31, wd = t >> 5;
    int idx = b * SCAN_BLK + t;
    int v = (idx < N) ? g_cnt[idx] : 0;
    int incl = warp_incl_scan(v, lane);
    if (lane == 31) wsum[wd] = incl;
    __syncthreads();
    if (wd == 0) {
        int s = (lane < 16) ? wsum[lane] : 0;
        s = warp_incl_scan(s, lane);
        if (lane < 16) wsum[lane] = s;
    }
    __syncthreads();
    int base = (wd > 0) ? wsum[wd - 1] : 0;
    incl += base;
    int excl = incl - v;
    if (idx <= N) g_rowptr[idx] = excl;     // includes idx == N sentinel
    if (idx < N)  g_cur[idx] = excl;
    if (t == SCAN_BLK - 1) g_blksum[b] = incl;
}

__global__ void scan2_kernel(int nb) {  // one 256-thread block; nb <= 256
    __shared__ int wsum[8];
    int t = threadIdx.x, lane = t & 31, wd = t >> 5;
    int v = (t < nb) ? g_blksum[t] : 0;
    int incl = warp_incl_scan(v, lane);
    if (lane == 31) wsum[wd] = incl;
    __syncthreads();
    if (wd == 0) {
        int s = (lane < 8) ? wsum[lane] : 0;
        s = warp_incl_scan(s, lane);
        if (lane < 8) wsum[lane] = s;
    }
    __syncthreads();
    int base = (wd > 0) ? wsum[wd - 1] : 0;
    if (t < nb) g_blksum[t] = incl + base - v;  // exclusive
}

__global__ void reorder_kernel(const void* __restrict__ ei, int E) {
    int i0 = (blockIdx.x * blockDim.x + threadIdx.x) * 4;
    if (i0 + 4 <= E) {
        int s0 = load_idx(ei, i0),     s1 = load_idx(ei, i0 + 1);
        int s2 = load_idx(ei, i0 + 2), s3 = load_idx(ei, i0 + 3);
        int d0 = load_idx(ei, (long long)E + i0);
        int d1 = load_idx(ei, (long long)E + i0 + 1);
        int d2 = load_idx(ei, (long long)E + i0 + 2);
        int d3 = load_idx(ei, (long long)E + i0 + 3);
        g_esrc[atomicAdd(&g_cur[d0], 1) + g_blksum[d0 >> 9]] = s0;
        g_esrc[atomicAdd(&g_cur[d1], 1) + g_blksum[d1 >> 9]] = s1;
        g_esrc[atomicAdd(&g_cur[d2], 1) + g_blksum[d2 >> 9]] = s2;
        g_esrc[atomicAdd(&g_cur[d3], 1) + g_blksum[d3 >> 9]] = s3;
    } else {
        for (int i = i0; i < E; i++) {
            int src = load_idx(ei, i);
            int dst = load_idx(ei, (long long)E + i);
            g_esrc[atomicAdd(&g_cur[dst], 1) + g_blksum[dst >> 9]] = src;
        }
    }
}

// ---------------------------------------------------------------------------
// Aggregation: one warp per node. acc = (1+eps)*x[i] + sum_j x[esrc[j]]
// (fp32 gathers + fp32 accumulation), rounded ONCE to fp16 on store.
// ---------------------------------------------------------------------------
__global__ void agg_kernel(const float4* __restrict__ x,
                           const float* __restrict__ eps, int N) {
    int w = (blockIdx.x * blockDim.x + threadIdx.x) >> 5;
    if (w >= N) return;
    int lane = threadIdx.x & 31;
    float s = 1.0f + eps[0];

    float4 a = x[(size_t)w * 32 + lane];
    float4 acc = make_float4(a.x * s, a.y * s, a.z * s, a.w * s);

    int j  = g_rowptr[w]     + g_blksum[w >> 9];
    int r1 = g_rowptr[w + 1] + g_blksum[(w + 1) >> 9];

#pragma unroll 1
    for (; j + 8 <= r1; j += 8) {
        int idx[8];
#pragma unroll
        for (int q = 0; q < 8; q++) idx[q] = g_esrc[j + q];
        float4 v[8];
#pragma unroll
        for (int q = 0; q < 8; q++) v[q] = x[(size_t)idx[q] * 32 + lane];
#pragma unroll
        for (int q = 0; q < 8; q++) {
            acc.x += v[q].x; acc.y += v[q].y;
            acc.z += v[q].z; acc.w += v[q].w;
        }
    }
    for (; j < r1; j++) {
        float4 v = x[(size_t)g_esrc[j] * 32 + lane];
        acc.x += v.x; acc.y += v.y; acc.z += v.z; acc.w += v.w;
    }
    uint2 o;
    o.x = pack_h2(acc.x, acc.y);
    o.y = pack_h2(acc.z, acc.w);
    ((uint2*)g_aggh)[(size_t)w * 32 + lane] = o;
}

// ---------------------------------------------------------------------------
// Fallback path (E > EDGES_MAX): fp32 init + atomic scatter, then convert.
// ---------------------------------------------------------------------------
__global__ void init_kernel(const float4* __restrict__ x,
                            const float* __restrict__ eps, int n4) {
    float s = 1.0f + eps[0];
    float4* agg = (float4*)g_agg;
    int i = blockIdx.x * blockDim.x + threadIdx.x;
    int stride = gridDim.x * blockDim.x;
    for (; i < n4; i += stride) {
        float4 v = x[i];
        v.x *= s; v.y *= s; v.z *= s; v.w *= s;
        agg[i] = v;
    }
}

__global__ void scatter_kernel(const float4* __restrict__ x,
                               const void* __restrict__ ei, int E) {
    int t = blockIdx.x * blockDim.x + threadIdx.x;
    int e = t >> 5;
    if (e >= E) return;
    int lane = t & 31;
    int src = load_idx(ei, e);
    int dst = load_idx(ei, (long long)E + e);
    float4 v = x[(size_t)src * 32 + lane];
    float* q = g_agg + (size_t)dst * 128 + lane * 4;
    asm volatile("red.global.add.v4.f32 [%0], {%1,%2,%3,%4};"
                 :: "l"(q), "f"(v.x), "f"(v.y), "f"(v.z), "f"(v.w)
                 : "memory");
}

__global__ void conv_kernel(int n4) {
    int i = blockIdx.x * blockDim.x + threadIdx.x;
    if (i >= n4) return;
    float4 v = ((const float4*)g_agg)[i];
    uint2 o;
    o.x = pack_h2(v.x, v.y);
    o.y = pack_h2(v.z, v.w);
    ((uint2*)g_aggh)[i] = o;
}

// ---------------------------------------------------------------------------
// Weight prep: Wt[n][k] = fp16(W[k][n])
// ---------------------------------------------------------------------------
__global__ void prep_w_kernel(const float* __restrict__ W1,
                              const float* __restrict__ W2) {
    int i = blockIdx.x * blockDim.x + threadIdx.x;
    if (i >= 2 * DIM * DIM) return;
    const float* W = (i < DIM * DIM) ? W1 : W2;
    __half* T = (i < DIM * DIM) ? g_wt1h : g_wt2h;
    int j = i & (DIM * DIM - 1);
    int nIdx = j >> 7;
    int k = j & 127;
    T[j] = __float2half_rn(W[k * DIM + nIdx]);
}

// ---------------------------------------------------------------------------
// Fused 2-layer fp16 tensor-core GEMM:
//   out[n,128] = relu(A @ W1 + b1) @ W2 + b2    (A = g_aggh fp16)
// One CTA per 256-row tile, 8 warps x 32 rows. Single-pass f16 m16n8k16
// (fp32 accum). Layer-1 epilogue writes fp16 h1 into the smem A buffer;
// W2 restaged into B buffer. Rows padded to 272B (17x16B, conflict-free
// ldmatrix — layout proven in the round-4 bf16 kernel).
// ---------------------------------------------------------------------------
#define PADB 272
#define SM_B_OFF 69632                 // 256*272
#define SMEM_GEMM_BYTES 104448         // 256*272 + 128*272

struct Frag { float v[2][16][4]; };

__device__ __forceinline__ void f16_mainloop(uint32_t aoff0, uint32_t aoff1,
                                             uint32_t boff, Frag& f) {
#pragma unroll
    for (int mt = 0; mt < 2; mt++)
#pragma unroll
        for (int nt = 0; nt < 16; nt++)
#pragma unroll
            for (int q = 0; q < 4; q++) f.v[mt][nt][q] = 0.0f;

#pragma unroll 1
    for (int ks = 0; ks < 8; ks++) {
        uint32_t kadd = ks * 32;          // 16 halfs per kstep
        uint32_t a0[4], a1[4];
        ldsm4(a0, aoff0 + kadd);
        ldsm4(a1, aoff1 + kadd);
#pragma unroll
        for (int ng = 0; ng < 8; ng++) {
            uint32_t b[4];
            ldsm4(b, boff + ng * (16 * PADB) + kadd);
            mma_f16(f.v[0][2 * ng],     a0, b[0], b[1]);
            mma_f16(f.v[1][2 * ng],     a1, b[0], b[1]);
            mma_f16(f.v[0][2 * ng + 1], a0, b[2], b[3]);
            mma_f16(f.v[1][2 * ng + 1], a1, b[2], b[3]);
        }
    }
}

__global__ void __launch_bounds__(256, 1)
gemm_fused_kernel(const __half* __restrict__ A,
                  const __half* __restrict__ B1t,
                  const float* __restrict__ b1,
                  const __half* __restrict__ B2t,
                  const float* __restrict__ b2,
                  float* __restrict__ out, int n) {
    extern __shared__ char smem[];
    uint32_t sb = smem_u32(smem);
    int tid = threadIdx.x, wid = tid >> 5, lane = tid & 31;
    int row0 = blockIdx.x * 256;

    // ---- Stage A (fp16, direct copy): 256 rows x 16 uint4 ----
    const uint4* A4 = (const uint4*)A;
#pragma unroll
    for (int i = 0; i < 16; i++) {
        int idx = tid + 256 * i;
        int r = idx >> 4, c = idx & 15;
        int gr = row0 + r;
        uint4 v = (gr < n) ? A4[(size_t)gr * 16 + c]
                           : make_uint4(0u, 0u, 0u, 0u);
        *(uint4*)(smem + r * PADB + c * 16) = v;
    }

    // ---- Stage B = W1t: 128 rows x 16 uint4 ----
    const uint4* B4 = (const uint4*)B1t;
#pragma unroll
    for (int i = 0; i < 8; i++) {
        int idx = tid + 256 * i;
        int r = idx >> 4, c = idx & 15;
        *(uint4*)(smem + SM_B_OFF + r * PADB + c * 16) = B4[idx];
    }
    __syncthreads();

    // ---- Per-lane ldmatrix base offsets (round-4 verified layout) ----
    int lr = lane & 7;
    int li = lane >> 3;
    // A x4: (r0,k0)(r8,k0)(r0,k8)(r8,k8)
    uint32_t aoff0 = sb + (wid * 32 + lr + (li & 1) * 8) * PADB +
                     ((li >> 1) * 8) * 2;
    uint32_t aoff1 = aoff0 + 16 * PADB;
    // B x4: (n0,k0)(n0,k8)(n8,k0)(n8,k8)
    uint32_t boff = sb + SM_B_OFF + (lr + (li >> 1) * 8) * PADB +
                    ((li & 1) * 8) * 2;

    Frag f;
    // ================= Layer 1 =================
    f16_mainloop(aoff0, aoff1, boff, f);
    __syncthreads();

    // ---- Restage B = W2t ----
    const uint4* B24 = (const uint4*)B2t;
#pragma unroll
    for (int i = 0; i < 8; i++) {
        int idx = tid + 256 * i;
        int r = idx >> 4, c = idx & 15;
        *(uint4*)(smem + SM_B_OFF + r * PADB + c * 16) = B24[idx];
    }

    // ---- Layer-1 epilogue into smem A: h1 = fp16(relu(acc + b1)) ----
#pragma unroll
    for (int nt = 0; nt < 16; nt++) {
        int col = nt * 8 + (lane & 3) * 2;
        float2 bv = *(const float2*)(b1 + col);
#pragma unroll
        for (int mt = 0; mt < 2; mt++) {
            int lrow = wid * 32 + mt * 16 + (lane >> 2);
            float* a = f.v[mt][nt];
            uint32_t p0 = pack_h2(fmaxf(a[0] + bv.x, 0.f),
                                  fmaxf(a[1] + bv.y, 0.f));
            uint32_t p1 = pack_h2(fmaxf(a[2] + bv.x, 0.f),
                                  fmaxf(a[3] + bv.y, 0.f));
            *(uint32_t*)(smem + lrow * PADB + col * 2)       = p0;
            *(uint32_t*)(smem + (lrow + 8) * PADB + col * 2) = p1;
        }
    }
    __syncthreads();

    // ================= Layer 2 =================
    f16_mainloop(aoff0, aoff1, boff, f);

    // ---- Final epilogue to gmem: out = acc + b2 ----
#pragma unroll
    for (int nt = 0; nt < 16; nt++) {
        int col = nt * 8 + (lane & 3) * 2;
        float2 bv = *(const float2*)(b2 + col);
#pragma unroll
        for (int mt = 0; mt < 2; mt++) {
            int r0 = row0 + wid * 32 + mt * 16 + (lane >> 2);
            float* a = f.v[mt][nt];
            if (r0 < n)
                *(float2*)(out + (size_t)r0 * 128 + col) =
                    make_float2(a[0] + bv.x, a[1] + bv.y);
            if (r0 + 8 < n)
                *(float2*)(out + (size_t)(r0 + 8) * 128 + col) =
                    make_float2(a[2] + bv.x, a[3] + bv.y);
        }
    }
}

// ---------------------------------------------------------------------------
extern "C" void kernel_launch(void* const* d_in, const int* in_sizes, int n_in,
                              void* d_out, int out_size) {
    const float* x   = (const float*)d_in[0];
    const void*  ei  = d_in[1];
    const float* W1  = (const float*)d_in[2];
    const float* b1  = (const float*)d_in[3];
    const float* W2  = (const float*)d_in[4];
    const float* b2  = (const float*)d_in[5];
    const float* eps = (const float*)d_in[6];

    int N = in_sizes[0] / DIM;
    int E = in_sizes[1] / 2;

    __half *aggh_ptr, *wt1_ptr, *wt2_ptr;
    int* cnt_ptr;
    cudaGetSymbolAddress((void**)&aggh_ptr, g_aggh);
    cudaGetSymbolAddress((void**)&wt1_ptr, g_wt1h);
    cudaGetSymbolAddress((void**)&wt2_ptr, g_wt2h);
    cudaGetSymbolAddress((void**)&cnt_ptr, g_cnt);

    detect_kernel<<<1, 32>>>((const unsigned int*)ei);
    prep_w_kernel<<<(2 * DIM * DIM + 255) / 256, 256>>>(W1, W2);

    if (E <= EDGES_MAX && N <= NNODES) {
        cudaMemsetAsync(cnt_ptr, 0, (size_t)N * sizeof(int), 0);
        int nthr4 = (E + 3) / 4;
        hist_kernel<<<(nthr4 + 255) / 256, 256>>>(ei, E);
        int nb_scan = (N + SCAN_BLK - 1) / SCAN_BLK;
        scan1_kernel<<<nb_scan, SCAN_BLK>>>(N);
        scan2_kernel<<<1, 256>>>(nb_scan);
        reorder_kernel<<<(nthr4 + 255) / 256, 256>>>(ei, E);
        agg_kernel<<<(N * 32 + 255) / 256, 256>>>((const float4*)x, eps, N);
    } else {
        int n4 = N * (DIM / 4);
        init_kernel<<<(n4 + 255) / 256, 256>>>((const float4*)x, eps, n4);
        long long tot = (long long)E * 32;
        scatter_kernel<<<(int)((tot + 255) / 256), 256>>>((const float4*)x, ei, E);
        conv_kernel<<<(n4 + 255) / 256, 256>>>(n4);
    }

    cudaFuncSetAttribute(gemm_fused_kernel,
                         cudaFuncAttributeMaxDynamicSharedMemorySize,
                         SMEM_GEMM_BYTES);
    int nb = (N + 255) / 256;
    gemm_fused_kernel<<<nb, 256, SMEM_GEMM_BYTES>>>(aggh_ptr, wt1_ptr, b1,
                                                    wt2_ptr, b2,
                                                    (float*)d_out, N);
}